// round 1
// baseline (speedup 1.0000x reference)
#include <cuda_runtime.h>
#include <cuda_bf16.h>

#define N_NODES 20000
#define N_EDGES 640000
#define HID 256
#define D_OP 140
#define D_EMB 64
#define D_CFG 52
#define LN_EPS 1e-5f

// ---------------- scratch (device globals; no allocation) ----------------
__device__ float g_x[N_NODES * HID];     // current features
__device__ float g_h[N_NODES * HID];     // GEMM output
__device__ float g_agg[N_NODES * HID];   // mean-aggregated neighbor features
__device__ int   g_deg[N_NODES];
__device__ float g_invdeg[N_NODES];
__device__ int   g_rowstart[N_NODES + 1];
__device__ int   g_cursor[N_NODES];
__device__ int   g_csr[N_EDGES];

// ---------------- graph preprocessing ----------------
__global__ void zero_kernel() {
    int i = blockIdx.x * blockDim.x + threadIdx.x;
    if (i < N_NODES) { g_deg[i] = 0; g_cursor[i] = 0; }
}

__global__ void deg_kernel(const int* __restrict__ dst) {
    int e = blockIdx.x * blockDim.x + threadIdx.x;
    if (e < N_EDGES) atomicAdd(&g_deg[dst[e]], 1);
}

__global__ void scan_kernel() {
    __shared__ int partial[256];
    int tid = threadIdx.x;
    const int CH = (N_NODES + 255) / 256;  // 79
    int base = tid * CH;
    int s = 0;
    for (int i = 0; i < CH; i++) {
        int idx = base + i;
        if (idx < N_NODES) s += g_deg[idx];
    }
    partial[tid] = s;
    __syncthreads();
    // inclusive Hillis-Steele scan
    for (int off = 1; off < 256; off <<= 1) {
        int v = 0;
        if (tid >= off) v = partial[tid - off];
        __syncthreads();
        partial[tid] += v;
        __syncthreads();
    }
    int run = (tid == 0) ? 0 : partial[tid - 1];
    for (int i = 0; i < CH; i++) {
        int idx = base + i;
        if (idx < N_NODES) {
            int d = g_deg[idx];
            g_rowstart[idx] = run;
            run += d;
            g_invdeg[idx] = 1.0f / fmaxf((float)d, 1.0f);
        }
    }
    if (tid == 255) g_rowstart[N_NODES] = run;  // == N_EDGES
}

__global__ void fill_kernel(const int* __restrict__ src, const int* __restrict__ dst) {
    int e = blockIdx.x * blockDim.x + threadIdx.x;
    if (e < N_EDGES) {
        int d = dst[e];
        int pos = atomicAdd(&g_cursor[d], 1);
        g_csr[g_rowstart[d] + pos] = src[e];
    }
}

// ---------------- input feature assembly ----------------
__global__ void build_x_kernel(const float* __restrict__ op_feats,
                               const float* __restrict__ cfg,
                               const float* __restrict__ emb,
                               const float* __restrict__ fmean,
                               const float* __restrict__ fstd,
                               const int* __restrict__ op_ids,
                               float* __restrict__ x) {
    int n = blockIdx.x;
    int c = threadIdx.x;
    float v;
    if (c < D_OP)               v = op_feats[n * D_OP + c];
    else if (c < D_OP + D_EMB)  v = emb[op_ids[n] * D_EMB + (c - D_OP)];
    else                        v = cfg[n * D_CFG + (c - D_OP - D_EMB)];
    x[n * HID + c] = (v - fmean[c]) / fstd[c];
}

// ---------------- neighbor mean aggregation via CSR ----------------
__global__ void agg_kernel() {
    int n = blockIdx.x;
    int t = threadIdx.x;  // 64 threads, each owns 4 channels (float4)
    int s0 = g_rowstart[n], s1 = g_rowstart[n + 1];
    const float4* xv = (const float4*)g_x;
    float4 acc = make_float4(0.f, 0.f, 0.f, 0.f);
    for (int j = s0; j < s1; j++) {
        int s = g_csr[j];
        float4 v = xv[s * (HID / 4) + t];
        acc.x += v.x; acc.y += v.y; acc.z += v.z; acc.w += v.w;
    }
    float id = g_invdeg[n];
    acc.x *= id; acc.y *= id; acc.z *= id; acc.w *= id;
    ((float4*)g_agg)[n * (HID / 4) + t] = acc;
}

// ---------------- fp32 GEMM: C[N,NC] = [A0 | A1][N,K] @ [B0 ; B1][K,NC] + bias ----------------
#define BM 128
#define BN 128
#define BK 16

__global__ __launch_bounds__(256) void gemm_kernel(
    const float* __restrict__ A0, const float* __restrict__ A1,
    const float* __restrict__ B0, const float* __restrict__ B1,
    const float* __restrict__ bias, float* __restrict__ C,
    int K, int NC)
{
    __shared__ float As[BM][BK + 1];
    __shared__ float Bs[BK][BN];

    int tid = threadIdx.x;
    int row0 = blockIdx.x * BM;
    int col0 = blockIdx.y * BN;
    int tx = tid & 15, ty = tid >> 4;

    float acc[8][8];
#pragma unroll
    for (int r = 0; r < 8; r++)
#pragma unroll
        for (int c = 0; c < 8; c++) acc[r][c] = 0.f;

    for (int k0 = 0; k0 < K; k0 += BK) {
        const float* Asrc; int ka;
        const float* Bsrc; int kb0;
        if (k0 < HID) { Asrc = A0; ka = k0;        Bsrc = B0; kb0 = k0; }
        else          { Asrc = A1; ka = k0 - HID;  Bsrc = B1; kb0 = k0 - HID; }

        // load A tile: BM x BK (A rows have stride HID)
#pragma unroll
        for (int r = 0; r < 2; r++) {
            int idx = tid + 256 * r;
            int m = idx >> 2, k4 = idx & 3;
            float4 v = make_float4(0.f, 0.f, 0.f, 0.f);
            int gm = row0 + m;
            if (gm < N_NODES) v = *(const float4*)&Asrc[gm * HID + ka + k4 * 4];
            As[m][k4 * 4 + 0] = v.x;
            As[m][k4 * 4 + 1] = v.y;
            As[m][k4 * 4 + 2] = v.z;
            As[m][k4 * 4 + 3] = v.w;
        }
        // load B tile: BK x BN (B rows have stride NC)
#pragma unroll
        for (int r = 0; r < 2; r++) {
            int idx = tid + 256 * r;
            int kb = idx >> 5, c4 = idx & 31;
            float4 v = *(const float4*)&Bsrc[(kb0 + kb) * NC + col0 + c4 * 4];
            *(float4*)&Bs[kb][c4 * 4] = v;
        }
        __syncthreads();

#pragma unroll
        for (int k = 0; k < BK; k++) {
            float a[8], b[8];
#pragma unroll
            for (int r = 0; r < 8; r++) a[r] = As[ty * 8 + r][k];
            float4 b0 = *(const float4*)&Bs[k][tx * 8];
            float4 b1 = *(const float4*)&Bs[k][tx * 8 + 4];
            b[0] = b0.x; b[1] = b0.y; b[2] = b0.z; b[3] = b0.w;
            b[4] = b1.x; b[5] = b1.y; b[6] = b1.z; b[7] = b1.w;
#pragma unroll
            for (int r = 0; r < 8; r++)
#pragma unroll
                for (int c = 0; c < 8; c++)
                    acc[r][c] += a[r] * b[c];
        }
        __syncthreads();
    }

    // epilogue
    float bv[8];
#pragma unroll
    for (int c = 0; c < 8; c++) bv[c] = bias ? bias[col0 + tx * 8 + c] : 0.f;

#pragma unroll
    for (int r = 0; r < 8; r++) {
        int gm = row0 + ty * 8 + r;
        if (gm < N_NODES) {
            float4 o0 = make_float4(acc[r][0] + bv[0], acc[r][1] + bv[1],
                                    acc[r][2] + bv[2], acc[r][3] + bv[3]);
            float4 o1 = make_float4(acc[r][4] + bv[4], acc[r][5] + bv[5],
                                    acc[r][6] + bv[6], acc[r][7] + bv[7]);
            *(float4*)&C[gm * NC + col0 + tx * 8] = o0;
            *(float4*)&C[gm * NC + col0 + tx * 8 + 4] = o1;
        }
    }
}

// ---------------- LayerNorm + ReLU (two-pass, matches reference formula) ----------------
__global__ void ln_relu_kernel(const float* __restrict__ in, float* __restrict__ out,
                               const float* __restrict__ gamma, const float* __restrict__ beta,
                               int D) {
    int row = blockIdx.x;
    int t = threadIdx.x;
    float v = in[row * D + t];

    __shared__ float ws[8];
    int w = t >> 5, l = t & 31, nw = D >> 5;

    // pass 1: mean
    float s = v;
#pragma unroll
    for (int o = 16; o; o >>= 1) s += __shfl_xor_sync(0xFFFFFFFFu, s, o);
    if (l == 0) ws[w] = s;
    __syncthreads();
    float tot = 0.f;
    for (int i = 0; i < nw; i++) tot += ws[i];
    float mu = tot / (float)D;
    __syncthreads();

    // pass 2: variance of deviations
    float d = v - mu;
    float s2 = d * d;
#pragma unroll
    for (int o = 16; o; o >>= 1) s2 += __shfl_xor_sync(0xFFFFFFFFu, s2, o);
    if (l == 0) ws[w] = s2;
    __syncthreads();
    float tot2 = 0.f;
    for (int i = 0; i < nw; i++) tot2 += ws[i];
    float var = tot2 / (float)D;

    float y = d * rsqrtf(var + LN_EPS) * gamma[t] + beta[t];
    out[row * D + t] = fmaxf(y, 0.f);
}

// ---------------- launch ----------------
extern "C" void kernel_launch(void* const* d_in, const int* in_sizes, int n_in,
                              void* d_out, int out_size) {
    const float* op_feats    = (const float*)d_in[0];
    const float* config_f    = (const float*)d_in[1];
    const float* embed_table = (const float*)d_in[2];
    const float* feat_mean   = (const float*)d_in[3];
    const float* feat_std    = (const float*)d_in[4];
    const float* Wself       = (const float*)d_in[5];   // [4,256,256]
    const float* Wneigh      = (const float*)d_in[6];   // [4,256,256]
    const float* bconv       = (const float*)d_in[7];   // [4,256]
    const float* conv_gamma  = (const float*)d_in[8];   // [4,256]
    const float* conv_beta   = (const float*)d_in[9];   // [4,256]
    const float* W1          = (const float*)d_in[10];  // [256,256]
    const float* g1          = (const float*)d_in[11];
    const float* b1          = (const float*)d_in[12];
    const float* W2          = (const float*)d_in[13];  // [256,128]
    const float* g2          = (const float*)d_in[14];
    const float* b2          = (const float*)d_in[15];
    const int*   op_ids      = (const int*)d_in[16];
    const int*   src         = (const int*)d_in[17];
    const int*   dst         = (const int*)d_in[18];
    float* out = (float*)d_out;

    float *xp, *hp, *aggp;
    cudaGetSymbolAddress((void**)&xp, g_x);
    cudaGetSymbolAddress((void**)&hp, g_h);
    cudaGetSymbolAddress((void**)&aggp, g_agg);

    // graph preprocessing
    zero_kernel<<<(N_NODES + 255) / 256, 256>>>();
    deg_kernel<<<(N_EDGES + 255) / 256, 256>>>(dst);
    scan_kernel<<<1, 256>>>();
    fill_kernel<<<(N_EDGES + 255) / 256, 256>>>(src, dst);

    // feature assembly
    build_x_kernel<<<N_NODES, HID>>>(op_feats, config_f, embed_table,
                                     feat_mean, feat_std, op_ids, xp);

    dim3 ggrid((N_NODES + BM - 1) / BM, HID / BN);   // 157 x 2
    dim3 ggrid2((N_NODES + BM - 1) / BM, 1);         // 157 x 1 (NC=128)

    for (int i = 0; i < 4; i++) {
        agg_kernel<<<N_NODES, 64>>>();
        gemm_kernel<<<ggrid, 256>>>(xp, aggp,
                                    Wself + i * HID * HID, Wneigh + i * HID * HID,
                                    bconv + i * HID, hp, 2 * HID, HID);
        ln_relu_kernel<<<N_NODES, HID>>>(hp, xp, conv_gamma + i * HID, conv_beta + i * HID, HID);
    }

    // head MLP
    gemm_kernel<<<ggrid, 256>>>(xp, nullptr, W1, nullptr, nullptr, hp, HID, HID);
    ln_relu_kernel<<<N_NODES, HID>>>(hp, xp, g1, b1, HID);

    gemm_kernel<<<ggrid2, 256>>>(xp, nullptr, W2, nullptr, nullptr, hp, HID, HID / 2);
    ln_relu_kernel<<<N_NODES, HID / 2>>>(hp, out, g2, b2, HID / 2);
}

// round 2
// speedup vs baseline: 1.6587x; 1.6587x over previous
#include <cuda_runtime.h>
#include <cuda_bf16.h>

#define N_NODES 20000
#define N_EDGES 640000
#define HID 256
#define D_OP 140
#define D_EMB 64
#define D_CFG 52
#define LN_EPS 1e-5f

// ---------------- scratch (device globals; no allocation) ----------------
__device__ float g_x[N_NODES * HID];
__device__ float g_h[N_NODES * HID];
__device__ float g_agg[N_NODES * HID];
__device__ int   g_deg[N_NODES];
__device__ float g_invdeg[N_NODES];
__device__ int   g_rowstart[N_NODES + 1];
__device__ int   g_cursor[N_NODES];
__device__ int   g_csr[N_EDGES];

// ---------------- graph preprocessing ----------------
__global__ void zero_kernel() {
    int i = blockIdx.x * blockDim.x + threadIdx.x;
    if (i < N_NODES) { g_deg[i] = 0; g_cursor[i] = 0; }
}

__global__ void deg_kernel(const int* __restrict__ dst) {
    int e = blockIdx.x * blockDim.x + threadIdx.x;
    if (e < N_EDGES) atomicAdd(&g_deg[dst[e]], 1);
}

__global__ void scan_kernel() {
    __shared__ int partial[256];
    int tid = threadIdx.x;
    const int CH = (N_NODES + 255) / 256;
    int base = tid * CH;
    int s = 0;
    for (int i = 0; i < CH; i++) {
        int idx = base + i;
        if (idx < N_NODES) s += g_deg[idx];
    }
    partial[tid] = s;
    __syncthreads();
    for (int off = 1; off < 256; off <<= 1) {
        int v = 0;
        if (tid >= off) v = partial[tid - off];
        __syncthreads();
        partial[tid] += v;
        __syncthreads();
    }
    int run = (tid == 0) ? 0 : partial[tid - 1];
    for (int i = 0; i < CH; i++) {
        int idx = base + i;
        if (idx < N_NODES) {
            int d = g_deg[idx];
            g_rowstart[idx] = run;
            run += d;
            g_invdeg[idx] = 1.0f / fmaxf((float)d, 1.0f);
        }
    }
    if (tid == 255) g_rowstart[N_NODES] = run;
}

__global__ void fill_kernel(const int* __restrict__ src, const int* __restrict__ dst) {
    int e = blockIdx.x * blockDim.x + threadIdx.x;
    if (e < N_EDGES) {
        int d = dst[e];
        int pos = atomicAdd(&g_cursor[d], 1);
        g_csr[g_rowstart[d] + pos] = src[e];
    }
}

// ---------------- input feature assembly ----------------
__global__ void build_x_kernel(const float* __restrict__ op_feats,
                               const float* __restrict__ cfg,
                               const float* __restrict__ emb,
                               const float* __restrict__ fmean,
                               const float* __restrict__ fstd,
                               const int* __restrict__ op_ids,
                               float* __restrict__ x) {
    int n = blockIdx.x;
    int c = threadIdx.x;
    float v;
    if (c < D_OP)               v = op_feats[n * D_OP + c];
    else if (c < D_OP + D_EMB)  v = emb[op_ids[n] * D_EMB + (c - D_OP)];
    else                        v = cfg[n * D_CFG + (c - D_OP - D_EMB)];
    x[n * HID + c] = (v - fmean[c]) / fstd[c];
}

// ---------------- neighbor mean aggregation via CSR ----------------
__global__ void agg_kernel() {
    int n = blockIdx.x;
    int t = threadIdx.x;
    int s0 = g_rowstart[n], s1 = g_rowstart[n + 1];
    const float4* xv = (const float4*)g_x;
    float4 acc = make_float4(0.f, 0.f, 0.f, 0.f);
    for (int j = s0; j < s1; j++) {
        int s = g_csr[j];
        float4 v = xv[s * (HID / 4) + t];
        acc.x += v.x; acc.y += v.y; acc.z += v.z; acc.w += v.w;
    }
    float id = g_invdeg[n];
    acc.x *= id; acc.y *= id; acc.z *= id; acc.w *= id;
    ((float4*)g_agg)[n * (HID / 4) + t] = acc;
}

// ---------------- TF32 tensor-core GEMM (tf32x3 compensated) ----------------
// C[N_NODES, NC] = [A0 | A1][.,K] @ [B0 ; B1][K, NC] + bias
// BM=128, BN=64, BK=32; 256 threads = 8 warps (4 m x 2 n); warp tile 32x32.

#define BM 128
#define BN 64
#define BK 32
#define A_STRIDE 36   // (4m + k) % 32 distinct for fragment reads
#define B_STRIDE 72   // (8k + n) % 32 distinct for fragment reads

__device__ __forceinline__ unsigned f2tf32(float x) {
    unsigned r;
    asm("cvt.rna.tf32.f32 %0, %1;" : "=r"(r) : "f"(x));
    return r;
}

__device__ __forceinline__ void mma_tf32(float* c, const unsigned* a, const unsigned* b) {
    asm volatile(
        "mma.sync.aligned.m16n8k8.row.col.f32.tf32.tf32.f32 "
        "{%0,%1,%2,%3}, {%4,%5,%6,%7}, {%8,%9}, {%0,%1,%2,%3};"
        : "+f"(c[0]), "+f"(c[1]), "+f"(c[2]), "+f"(c[3])
        : "r"(a[0]), "r"(a[1]), "r"(a[2]), "r"(a[3]), "r"(b[0]), "r"(b[1]));
}

__global__ __launch_bounds__(256) void gemm_tf32_kernel(
    const float* __restrict__ A0, const float* __restrict__ A1,
    const float* __restrict__ B0, const float* __restrict__ B1,
    const float* __restrict__ bias, float* __restrict__ C,
    int K, int NC)
{
    extern __shared__ float smem[];
    float* Ah = smem;                          // [BM][A_STRIDE]
    float* Al = Ah + BM * A_STRIDE;
    float* Bh = Al + BM * A_STRIDE;            // [BK][B_STRIDE]
    float* Bl = Bh + BK * B_STRIDE;

    int tid = threadIdx.x;
    int lane = tid & 31, wid = tid >> 5;
    int warp_m = wid & 3, warp_n = wid >> 2;   // 4 x 2
    int g = lane >> 2, tig = lane & 3;

    int row0 = blockIdx.x * BM;
    int col0 = blockIdx.y * BN;

    float acc[2][4][4];
#pragma unroll
    for (int mt = 0; mt < 2; mt++)
#pragma unroll
        for (int nt = 0; nt < 4; nt++)
#pragma unroll
            for (int i = 0; i < 4; i++) acc[mt][nt][i] = 0.f;

    for (int k0 = 0; k0 < K; k0 += BK) {
        const float* Asrc; int ka;
        const float* Bsrc; int kb0;
        if (k0 < HID) { Asrc = A0; ka = k0;       Bsrc = B0; kb0 = k0; }
        else          { Asrc = A1; ka = k0 - HID; Bsrc = B1; kb0 = k0 - HID; }

        // --- load A tile: BM x BK, split into hi/lo at store ---
#pragma unroll
        for (int r = 0; r < 4; r++) {
            int idx = tid + 256 * r;            // 1024 float4s
            int m = idx >> 3, k4 = (idx & 7) * 4;
            float4 v = make_float4(0.f, 0.f, 0.f, 0.f);
            int gm = row0 + m;
            if (gm < N_NODES) v = *(const float4*)&Asrc[gm * HID + ka + k4];
            float vv[4] = {v.x, v.y, v.z, v.w};
#pragma unroll
            for (int i = 0; i < 4; i++) {
                unsigned hb = f2tf32(vv[i]);
                float hf = __uint_as_float(hb);
                float lo = vv[i] - hf;
                Ah[m * A_STRIDE + k4 + i] = hf;
                Al[m * A_STRIDE + k4 + i] = __uint_as_float(f2tf32(lo));
            }
        }
        // --- load B tile: BK x BN, split into hi/lo ---
#pragma unroll
        for (int r = 0; r < 2; r++) {
            int idx = tid + 256 * r;            // 512 float4s
            int n4 = (idx & 15) * 4, kk = idx >> 4;
            float4 v = *(const float4*)&Bsrc[(kb0 + kk) * NC + col0 + n4];
            float vv[4] = {v.x, v.y, v.z, v.w};
#pragma unroll
            for (int i = 0; i < 4; i++) {
                unsigned hb = f2tf32(vv[i]);
                float hf = __uint_as_float(hb);
                float lo = vv[i] - hf;
                Bh[kk * B_STRIDE + n4 + i] = hf;
                Bl[kk * B_STRIDE + n4 + i] = __uint_as_float(f2tf32(lo));
            }
        }
        __syncthreads();

#pragma unroll
        for (int ks = 0; ks < BK / 8; ks++) {
            unsigned ah[2][4], al[2][4], bh[4][2], bl[4][2];
#pragma unroll
            for (int mt = 0; mt < 2; mt++) {
                int mrow = warp_m * 32 + mt * 16 + g;
                int kc = ks * 8 + tig;
                ah[mt][0] = __float_as_uint(Ah[mrow * A_STRIDE + kc]);
                ah[mt][1] = __float_as_uint(Ah[(mrow + 8) * A_STRIDE + kc]);
                ah[mt][2] = __float_as_uint(Ah[mrow * A_STRIDE + kc + 4]);
                ah[mt][3] = __float_as_uint(Ah[(mrow + 8) * A_STRIDE + kc + 4]);
                al[mt][0] = __float_as_uint(Al[mrow * A_STRIDE + kc]);
                al[mt][1] = __float_as_uint(Al[(mrow + 8) * A_STRIDE + kc]);
                al[mt][2] = __float_as_uint(Al[mrow * A_STRIDE + kc + 4]);
                al[mt][3] = __float_as_uint(Al[(mrow + 8) * A_STRIDE + kc + 4]);
            }
#pragma unroll
            for (int nt = 0; nt < 4; nt++) {
                int ncol = warp_n * 32 + nt * 8 + g;
                int kr = ks * 8 + tig;
                bh[nt][0] = __float_as_uint(Bh[kr * B_STRIDE + ncol]);
                bh[nt][1] = __float_as_uint(Bh[(kr + 4) * B_STRIDE + ncol]);
                bl[nt][0] = __float_as_uint(Bl[kr * B_STRIDE + ncol]);
                bl[nt][1] = __float_as_uint(Bl[(kr + 4) * B_STRIDE + ncol]);
            }
#pragma unroll
            for (int mt = 0; mt < 2; mt++)
#pragma unroll
                for (int nt = 0; nt < 4; nt++) {
                    mma_tf32(acc[mt][nt], ah[mt], bh[nt]);   // hi*hi
                    mma_tf32(acc[mt][nt], al[mt], bh[nt]);   // lo*hi
                    mma_tf32(acc[mt][nt], ah[mt], bl[nt]);   // hi*lo
                }
        }
        __syncthreads();
    }

    // epilogue
#pragma unroll
    for (int nt = 0; nt < 4; nt++) {
        int gc = col0 + warp_n * 32 + nt * 8 + 2 * tig;
        float b0 = bias ? bias[gc] : 0.f;
        float b1 = bias ? bias[gc + 1] : 0.f;
#pragma unroll
        for (int mt = 0; mt < 2; mt++) {
            int gr0 = row0 + warp_m * 32 + mt * 16 + g;
            if (gr0 < N_NODES) {
                float2 o = make_float2(acc[mt][nt][0] + b0, acc[mt][nt][1] + b1);
                *(float2*)&C[gr0 * NC + gc] = o;
            }
            int gr1 = gr0 + 8;
            if (gr1 < N_NODES) {
                float2 o = make_float2(acc[mt][nt][2] + b0, acc[mt][nt][3] + b1);
                *(float2*)&C[gr1 * NC + gc] = o;
            }
        }
    }
}

#define GEMM_SMEM ((2 * BM * A_STRIDE + 2 * BK * B_STRIDE) * 4)

// ---------------- LayerNorm + ReLU ----------------
__global__ void ln_relu_kernel(const float* __restrict__ in, float* __restrict__ out,
                               const float* __restrict__ gamma, const float* __restrict__ beta,
                               int D) {
    int row = blockIdx.x;
    int t = threadIdx.x;
    float v = in[row * D + t];

    __shared__ float ws[8];
    int w = t >> 5, l = t & 31, nw = D >> 5;

    float s = v;
#pragma unroll
    for (int o = 16; o; o >>= 1) s += __shfl_xor_sync(0xFFFFFFFFu, s, o);
    if (l == 0) ws[w] = s;
    __syncthreads();
    float tot = 0.f;
    for (int i = 0; i < nw; i++) tot += ws[i];
    float mu = tot / (float)D;
    __syncthreads();

    float d = v - mu;
    float s2 = d * d;
#pragma unroll
    for (int o = 16; o; o >>= 1) s2 += __shfl_xor_sync(0xFFFFFFFFu, s2, o);
    if (l == 0) ws[w] = s2;
    __syncthreads();
    float tot2 = 0.f;
    for (int i = 0; i < nw; i++) tot2 += ws[i];
    float var = tot2 / (float)D;

    float y = d * rsqrtf(var + LN_EPS) * gamma[t] + beta[t];
    out[row * D + t] = fmaxf(y, 0.f);
}

// ---------------- launch ----------------
extern "C" void kernel_launch(void* const* d_in, const int* in_sizes, int n_in,
                              void* d_out, int out_size) {
    const float* op_feats    = (const float*)d_in[0];
    const float* config_f    = (const float*)d_in[1];
    const float* embed_table = (const float*)d_in[2];
    const float* feat_mean   = (const float*)d_in[3];
    const float* feat_std    = (const float*)d_in[4];
    const float* Wself       = (const float*)d_in[5];
    const float* Wneigh      = (const float*)d_in[6];
    const float* bconv       = (const float*)d_in[7];
    const float* conv_gamma  = (const float*)d_in[8];
    const float* conv_beta   = (const float*)d_in[9];
    const float* W1          = (const float*)d_in[10];
    const float* g1          = (const float*)d_in[11];
    const float* b1          = (const float*)d_in[12];
    const float* W2          = (const float*)d_in[13];
    const float* g2          = (const float*)d_in[14];
    const float* b2          = (const float*)d_in[15];
    const int*   op_ids      = (const int*)d_in[16];
    const int*   src         = (const int*)d_in[17];
    const int*   dst         = (const int*)d_in[18];
    float* out = (float*)d_out;

    float *xp, *hp, *aggp;
    cudaGetSymbolAddress((void**)&xp, g_x);
    cudaGetSymbolAddress((void**)&hp, g_h);
    cudaGetSymbolAddress((void**)&aggp, g_agg);

    cudaFuncSetAttribute(gemm_tf32_kernel,
                         cudaFuncAttributeMaxDynamicSharedMemorySize, GEMM_SMEM);

    zero_kernel<<<(N_NODES + 255) / 256, 256>>>();
    deg_kernel<<<(N_EDGES + 255) / 256, 256>>>(dst);
    scan_kernel<<<1, 256>>>();
    fill_kernel<<<(N_EDGES + 255) / 256, 256>>>(src, dst);

    build_x_kernel<<<N_NODES, HID>>>(op_feats, config_f, embed_table,
                                     feat_mean, feat_std, op_ids, xp);

    dim3 ggrid((N_NODES + BM - 1) / BM, HID / BN);       // 157 x 4
    dim3 ggrid2((N_NODES + BM - 1) / BM, (HID / 2) / BN); // 157 x 2

    for (int i = 0; i < 4; i++) {
        agg_kernel<<<N_NODES, 64>>>();
        gemm_tf32_kernel<<<ggrid, 256, GEMM_SMEM>>>(
            xp, aggp, Wself + i * HID * HID, Wneigh + i * HID * HID,
            bconv + i * HID, hp, 2 * HID, HID);
        ln_relu_kernel<<<N_NODES, HID>>>(hp, xp, conv_gamma + i * HID, conv_beta + i * HID, HID);
    }

    gemm_tf32_kernel<<<ggrid, 256, GEMM_SMEM>>>(xp, nullptr, W1, nullptr, nullptr, hp, HID, HID);
    ln_relu_kernel<<<N_NODES, HID>>>(hp, xp, g1, b1, HID);

    gemm_tf32_kernel<<<ggrid2, 256, GEMM_SMEM>>>(xp, nullptr, W2, nullptr, nullptr, hp, HID, HID / 2);
    ln_relu_kernel<<<N_NODES, HID / 2>>>(hp, out, g2, b2, HID / 2);
}